// round 13
// baseline (speedup 1.0000x reference)
#include <cuda_runtime.h>

// CumulantSOAP: per-column mean/var of X (200000 x 576 f32) -> (cum - mu) @ W (1728x4) -> 4 floats.
// Single pass (S1, S2); mom1 treated as 0 (pure fp rounding residual).
//
// R11: single kernel. R4-R10 showed any separate stage-2 kernel costs ~10-12us regardless of
// geometry (launch + straggler tail + partials evicted to DRAM + low-occupancy latency).
// Now each block REDGs its 1152 column partials into g_S1/g_S2 (740 adds/address ~ 0.9cyc each,
// overlapped with block-finish stagger), and the last-finishing block (int counter) reads the
// 9KB totals from L2, projects, writes out[4], and re-zeroes state for graph replay.

#define NROWS   200000
#define PCOLS   576
#define PV      144                       // float4 groups per row
#define TOTALV  ((size_t)NROWS * PV)      // 28,800,000 float4
#define BLK1    288
#define G1      740

__device__ float g_S1[PCOLS];             // zero-init; restored to zero at kernel exit
__device__ float g_S2[PCOLS];
__device__ int   g_count = 0;

__global__ __launch_bounds__(BLK1) void k1_fused(const float* __restrict__ X,
                                                 const float* __restrict__ mu,
                                                 const float* __restrict__ W,
                                                 float* __restrict__ out) {
    const float4* __restrict__ Xv = reinterpret_cast<const float4*>(X);
    const int tid = threadIdx.x;

    float s1x = 0.f, s1y = 0.f, s1z = 0.f, s1w = 0.f;
    float s2x = 0.f, s2y = 0.f, s2z = 0.f, s2w = 0.f;

    size_t i = (size_t)blockIdx.x * BLK1 + tid;
    const size_t stride = (size_t)G1 * BLK1;   // 213120, divisible by 144

    for (; i + 3 * stride < TOTALV; i += 4 * stride) {
        float4 a = __ldcs(Xv + i);
        float4 b = __ldcs(Xv + i + stride);
        float4 c = __ldcs(Xv + i + 2 * stride);
        float4 d = __ldcs(Xv + i + 3 * stride);

        s1x += a.x; s1y += a.y; s1z += a.z; s1w += a.w;
        s2x = fmaf(a.x, a.x, s2x); s2y = fmaf(a.y, a.y, s2y);
        s2z = fmaf(a.z, a.z, s2z); s2w = fmaf(a.w, a.w, s2w);

        s1x += b.x; s1y += b.y; s1z += b.z; s1w += b.w;
        s2x = fmaf(b.x, b.x, s2x); s2y = fmaf(b.y, b.y, s2y);
        s2z = fmaf(b.z, b.z, s2z); s2w = fmaf(b.w, b.w, s2w);

        s1x += c.x; s1y += c.y; s1z += c.z; s1w += c.w;
        s2x = fmaf(c.x, c.x, s2x); s2y = fmaf(c.y, c.y, s2y);
        s2z = fmaf(c.z, c.z, s2z); s2w = fmaf(c.w, c.w, s2w);

        s1x += d.x; s1y += d.y; s1z += d.z; s1w += d.w;
        s2x = fmaf(d.x, d.x, s2x); s2y = fmaf(d.y, d.y, s2y);
        s2z = fmaf(d.z, d.z, s2z); s2w = fmaf(d.w, d.w, s2w);
    }
    for (; i < TOTALV; i += stride) {
        float4 a = __ldcs(Xv + i);
        s1x += a.x; s1y += a.y; s1z += a.z; s1w += a.w;
        s2x = fmaf(a.x, a.x, s2x); s2y = fmaf(a.y, a.y, s2y);
        s2z = fmaf(a.z, a.z, s2z); s2w = fmaf(a.w, a.w, s2w);
    }

    // ---- pair-reduce: tid and tid+144 share the same column group (tid % 144) ----
    __shared__ float red[PV][8];
    if (tid >= PV) {
        float* r = red[tid - PV];
        r[0] = s1x; r[1] = s1y; r[2] = s1z; r[3] = s1w;
        r[4] = s2x; r[5] = s2y; r[6] = s2z; r[7] = s2w;
    }
    __syncthreads();
    if (tid < PV) {
        const float* r = red[tid];
        int col = 4 * tid;
        atomicAdd(&g_S1[col    ], s1x + r[0]);
        atomicAdd(&g_S1[col + 1], s1y + r[1]);
        atomicAdd(&g_S1[col + 2], s1z + r[2]);
        atomicAdd(&g_S1[col + 3], s1w + r[3]);
        atomicAdd(&g_S2[col    ], s2x + r[4]);
        atomicAdd(&g_S2[col + 1], s2y + r[5]);
        atomicAdd(&g_S2[col + 2], s2z + r[6]);
        atomicAdd(&g_S2[col + 3], s2w + r[7]);
    }

    // ---- last-block detection ----
    __shared__ int s_last;
    __threadfence();
    __syncthreads();
    if (tid == 0) s_last = (atomicAdd(&g_count, 1) == G1 - 1);
    __syncthreads();
    if (!s_last) return;
    __threadfence();

    // ---- last block: projection on the 1152 totals (L2-resident, 9 KB) ----
    __shared__ float sred[PV][4];
    if (tid < PV) {
        const float invN = 1.0f / (float)NROWS;
        float acc[4] = {0.f, 0.f, 0.f, 0.f};
        #pragma unroll
        for (int c = 0; c < 4; c++) {
            int col  = 4 * tid + c;
            int base = 3 * col;
            float S1 = __ldcg(&g_S1[col]);
            float S2 = __ldcg(&g_S2[col]);
            float m    = S1 * invN;
            float mom2 = fmaf(-m, m, S2 * invN);   // E[x^2] - m^2
            float c0 = m    - __ldg(mu + base);
            float c1 =      - __ldg(mu + base + 1);  // mom1 ~ 0
            float c2 = mom2 - __ldg(mu + base + 2);
            #pragma unroll
            for (int k = 0; k < 4; k++) {
                float w0 = __ldg(W + (base    ) * 4 + k);
                float w1 = __ldg(W + (base + 1) * 4 + k);
                float w2 = __ldg(W + (base + 2) * 4 + k);
                acc[k] = fmaf(c0, w0, fmaf(c1, w1, fmaf(c2, w2, acc[k])));
            }
        }
        #pragma unroll
        for (int k = 0; k < 4; k++) sred[tid][k] = acc[k];
    }
    __syncthreads();
    if (tid < 64) {
        #pragma unroll
        for (int k = 0; k < 4; k++) {
            float v = sred[tid][k] + sred[tid + 64][k];
            if (tid < 16) v += sred[tid + 128][k];
            sred[tid][k] = v;
        }
    }
    __syncthreads();
    if (tid < 32) {
        #pragma unroll
        for (int k = 0; k < 4; k++) sred[tid][k] += sred[tid + 32][k];
    }
    __syncthreads();
    if (tid < 4) {
        float v = 0.f;
        #pragma unroll
        for (int j = 0; j < 32; j++) v += sred[j][tid];
        out[tid] = v;
    }

    // ---- restore state for next graph replay ----
    for (int c = tid; c < PCOLS; c += BLK1) {
        g_S1[c] = 0.f;
        g_S2[c] = 0.f;
    }
    if (tid == 0) g_count = 0;
}

extern "C" void kernel_launch(void* const* d_in, const int* in_sizes, int n_in,
                              void* d_out, int out_size) {
    const float* X  = (const float*)d_in[0];
    const float* mu = (const float*)d_in[1];
    const float* W  = (const float*)d_in[2];
    float* out = (float*)d_out;

    k1_fused<<<G1, BLK1>>>(X, mu, W, out);
}

// round 17
// speedup vs baseline: 1.1188x; 1.1188x over previous
#include <cuda_runtime.h>

// CumulantSOAP: per-column mean/var of X (200000 x 576 f32) -> (cum - mu) @ W (1728x4) -> 4 floats.
// Single pass (S1, S2); mom1 treated as 0 (pure fp rounding residual).
//
// R14: K1 reverted to the exact R7 binary (66.6us, ~86% of HBM — at the wall; its codegen is
// fragile: R11 showed adding an epilogue drops regs 38->34 and kills load batching).
// Stage 2 rebuilt: 148 blocks (all SMs), 5 coalesced rows each, REDG atomicAdd into
// g_S1/g_S2[576] (spread addresses, ~1.3cyc/lane), last block projects from 9KB L2 totals.

#define NROWS   200000
#define PCOLS   576
#define PV      144                       // float4 groups per row
#define TOTALV  ((size_t)NROWS * PV)      // 28,800,000 float4
#define BLK1    288
#define G1      740
#define G2      148
#define RPB     5                         // G1 / G2

__device__ float g_s1[(size_t)G1 * PCOLS];   // [block][col] partial sum x
__device__ float g_s2[(size_t)G1 * PCOLS];   // [block][col] partial sum x^2
__device__ float g_S1[PCOLS];                // zero-init; re-zeroed at stage-2 exit
__device__ float g_S2[PCOLS];
__device__ int   g_count = 0;

// -------------------- Stage 1 (R7 binary — do not touch) --------------------
__global__ __launch_bounds__(BLK1) void k1_colsums(const float* __restrict__ X) {
    const float4* __restrict__ Xv = reinterpret_cast<const float4*>(X);
    const int tid = threadIdx.x;

    float s1x = 0.f, s1y = 0.f, s1z = 0.f, s1w = 0.f;
    float s2x = 0.f, s2y = 0.f, s2z = 0.f, s2w = 0.f;

    size_t i = (size_t)blockIdx.x * BLK1 + tid;
    const size_t stride = (size_t)G1 * BLK1;   // 213120, divisible by 144

    for (; i + 3 * stride < TOTALV; i += 4 * stride) {
        float4 a = __ldcs(Xv + i);
        float4 b = __ldcs(Xv + i + stride);
        float4 c = __ldcs(Xv + i + 2 * stride);
        float4 d = __ldcs(Xv + i + 3 * stride);

        s1x += a.x; s1y += a.y; s1z += a.z; s1w += a.w;
        s2x = fmaf(a.x, a.x, s2x); s2y = fmaf(a.y, a.y, s2y);
        s2z = fmaf(a.z, a.z, s2z); s2w = fmaf(a.w, a.w, s2w);

        s1x += b.x; s1y += b.y; s1z += b.z; s1w += b.w;
        s2x = fmaf(b.x, b.x, s2x); s2y = fmaf(b.y, b.y, s2y);
        s2z = fmaf(b.z, b.z, s2z); s2w = fmaf(b.w, b.w, s2w);

        s1x += c.x; s1y += c.y; s1z += c.z; s1w += c.w;
        s2x = fmaf(c.x, c.x, s2x); s2y = fmaf(c.y, c.y, s2y);
        s2z = fmaf(c.z, c.z, s2z); s2w = fmaf(c.w, c.w, s2w);

        s1x += d.x; s1y += d.y; s1z += d.z; s1w += d.w;
        s2x = fmaf(d.x, d.x, s2x); s2y = fmaf(d.y, d.y, s2y);
        s2z = fmaf(d.z, d.z, s2z); s2w = fmaf(d.w, d.w, s2w);
    }
    for (; i < TOTALV; i += stride) {
        float4 a = __ldcs(Xv + i);
        s1x += a.x; s1y += a.y; s1z += a.z; s1w += a.w;
        s2x = fmaf(a.x, a.x, s2x); s2y = fmaf(a.y, a.y, s2y);
        s2z = fmaf(a.z, a.z, s2z); s2w = fmaf(a.w, a.w, s2w);
    }

    __shared__ float red[PV][8];
    if (tid >= PV) {
        float* r = red[tid - PV];
        r[0] = s1x; r[1] = s1y; r[2] = s1z; r[3] = s1w;
        r[4] = s2x; r[5] = s2y; r[6] = s2z; r[7] = s2w;
    }
    __syncthreads();
    if (tid < PV) {
        const float* r = red[tid];
        float4 o1 = make_float4(s1x + r[0], s1y + r[1], s1z + r[2], s1w + r[3]);
        float4 o2 = make_float4(s2x + r[4], s2y + r[5], s2z + r[6], s2w + r[7]);
        reinterpret_cast<float4*>(g_s1)[(size_t)blockIdx.x * PV + tid] = o1;
        reinterpret_cast<float4*>(g_s2)[(size_t)blockIdx.x * PV + tid] = o2;
    }
}

__device__ __forceinline__ float4 f4add(float4 a, float4 b) {
    return make_float4(a.x + b.x, a.y + b.y, a.z + b.z, a.w + b.w);
}

// -------- Stage 2: all-SM reduce via REDG + last-block projection --------
__global__ __launch_bounds__(576) void k2_project(const float* __restrict__ mu,
                                                  const float* __restrict__ W,
                                                  float* __restrict__ out) {
    const int tid = threadIdx.x;
    const int g  = tid % PV;           // float4 column group
    const int ar = (tid / PV) & 1;     // 0 -> s1, 1 -> s2
    const int ph = tid / (2 * PV);     // row phase 0..1

    // ---- reduce this block's 5 rows (coalesced), REDG into global totals ----
    {
        const float4* __restrict__ src =
            reinterpret_cast<const float4*>(ar ? g_s2 : g_s1);
        const size_t rb = (size_t)blockIdx.x * RPB;
        float4 acc = make_float4(0.f, 0.f, 0.f, 0.f);
        #pragma unroll
        for (int r = ph; r < RPB; r += 2)     // ph0: 0,2,4  ph1: 1,3
            acc = f4add(acc, __ldcg(src + (rb + r) * PV + g));

        float* dst = (ar ? g_S2 : g_S1) + 4 * g;
        atomicAdd(dst,     acc.x);
        atomicAdd(dst + 1, acc.y);
        atomicAdd(dst + 2, acc.z);
        atomicAdd(dst + 3, acc.w);
    }

    // ---- last-block detection ----
    __shared__ int s_last;
    __threadfence();
    __syncthreads();
    if (tid == 0) s_last = (atomicAdd(&g_count, 1) == G2 - 1);
    __syncthreads();
    if (!s_last) return;
    __threadfence();

    // ---- projection on the 1152 totals (9 KB, L2-resident) ----
    __shared__ float sred[PV][4];
    if (tid < PV) {
        const float invN = 1.0f / (float)NROWS;
        float acc[4] = {0.f, 0.f, 0.f, 0.f};
        #pragma unroll
        for (int c = 0; c < 4; c++) {
            int col  = 4 * tid + c;
            int base = 3 * col;
            float S1 = __ldcg(&g_S1[col]);
            float S2 = __ldcg(&g_S2[col]);
            float m    = S1 * invN;
            float mom2 = fmaf(-m, m, S2 * invN);     // E[x^2] - m^2
            float c0 = m    - __ldg(mu + base);
            float c1 =      - __ldg(mu + base + 1);  // mom1 ~ 0
            float c2 = mom2 - __ldg(mu + base + 2);
            #pragma unroll
            for (int k = 0; k < 4; k++) {
                float w0 = __ldg(W + (base    ) * 4 + k);
                float w1 = __ldg(W + (base + 1) * 4 + k);
                float w2 = __ldg(W + (base + 2) * 4 + k);
                acc[k] = fmaf(c0, w0, fmaf(c1, w1, fmaf(c2, w2, acc[k])));
            }
        }
        #pragma unroll
        for (int k = 0; k < 4; k++) sred[tid][k] = acc[k];
    }
    __syncthreads();
    if (tid < 64) {
        #pragma unroll
        for (int k = 0; k < 4; k++) {
            float v = sred[tid][k] + sred[tid + 64][k];
            if (tid < 16) v += sred[tid + 128][k];
            sred[tid][k] = v;
        }
    }
    __syncthreads();
    if (tid < 32) {
        #pragma unroll
        for (int k = 0; k < 4; k++) sred[tid][k] += sred[tid + 32][k];
    }
    __syncthreads();
    if (tid < 4) {
        float v = 0.f;
        #pragma unroll
        for (int j = 0; j < 32; j++) v += sred[j][tid];
        out[tid] = v;
    }

    // ---- restore state for next graph replay ----
    if (tid < PCOLS) {
        g_S1[tid] = 0.f;
        g_S2[tid] = 0.f;
    }
    if (tid == 0) g_count = 0;
}

extern "C" void kernel_launch(void* const* d_in, const int* in_sizes, int n_in,
                              void* d_out, int out_size) {
    const float* X  = (const float*)d_in[0];
    const float* mu = (const float*)d_in[1];
    const float* W  = (const float*)d_in[2];
    float* out = (float*)d_out;

    k1_colsums<<<G1, BLK1>>>(X);
    k2_project<<<G2, 576>>>(mu, W, out);
}